// round 1
// baseline (speedup 1.0000x reference)
#include <cuda_runtime.h>
#include <cstdint>

#define T_STEPS 256
#define BATCH   128
#define DIN     1024
#define HID     1024
#define NGATE   4096  // 4*HID

// Scratch (device globals; no allocation allowed in kernel_launch).
__device__ float g_G[(size_t)T_STEPS * BATCH * NGATE];  // precomputed x@Wx + b  (512 MB)
__device__ float g_h[2][BATCH * HID];                   // double-buffered hidden state
__device__ float g_c[BATCH * HID];                      // cell state

// ---------------- helpers ----------------

__device__ __forceinline__ float f2tf32(float x) {
    uint32_t u;
    asm("cvt.rna.tf32.f32 %0, %1;" : "=r"(u) : "f"(x));
    return __uint_as_float(u);
}

__device__ __forceinline__ void mma_tf32(float c[4], const uint32_t a[4], const uint32_t b[2]) {
    asm volatile(
        "mma.sync.aligned.m16n8k8.row.col.f32.tf32.tf32.f32 "
        "{%0,%1,%2,%3}, {%4,%5,%6,%7}, {%8,%9}, {%0,%1,%2,%3};"
        : "+f"(c[0]), "+f"(c[1]), "+f"(c[2]), "+f"(c[3])
        : "r"(a[0]), "r"(a[1]), "r"(a[2]), "r"(a[3]), "r"(b[0]), "r"(b[1]));
}

__device__ __forceinline__ float sigmoidf_fast(float x) {
    x = fminf(fmaxf(x, -30.f), 30.f);
    return __fdividef(1.f, 1.f + __expf(-x));
}

__device__ __forceinline__ float tanhf_fast(float x) {
    x = fminf(fmaxf(x, -15.f), 15.f);
    float e = __expf(2.f * x);
    return __fdividef(e - 1.f, e + 1.f);
}

// ---------------- init state ----------------

__global__ void init_state(const float* __restrict__ csh) {
    int idx = blockIdx.x * blockDim.x + threadIdx.x;
    if (idx < BATCH * HID) {
        int b = idx / HID, j = idx % HID;
        g_c[idx]    = csh[b * 2 * HID + j];          // cell first
        g_h[0][idx] = csh[b * 2 * HID + HID + j];    // hidden second
    }
}

// ---------------- pre-GEMM: G = x @ Wx + bias ----------------
// M = T*B = 32768, N = 4096, K = 1024. Tile 128x128x32, 256 threads,
// 8 warps arranged 4(M) x 2(N), warp tile 32x64 via m16n8k8 tf32.

__global__ __launch_bounds__(256) void pregemm(const float* __restrict__ x,
                                               const float* __restrict__ Wx,
                                               const float* __restrict__ bias) {
    __shared__ float As[128 * 36];   // stride 36 -> conflict-free frag loads
    __shared__ float Bs[32 * 136];   // stride 136 -> conflict-free frag loads

    const int tid  = threadIdx.x;
    const int warp = tid >> 5, lane = tid & 31;
    const int g  = lane >> 2, t4 = lane & 3;
    const int wm = warp >> 1, wn = warp & 1;
    const int m0 = blockIdx.y * 128;
    const int n0 = blockIdx.x * 128;

    float acc[2][8][4];
#pragma unroll
    for (int a = 0; a < 2; a++)
#pragma unroll
        for (int b = 0; b < 8; b++)
#pragma unroll
            for (int c = 0; c < 4; c++) acc[a][b][c] = 0.f;

    for (int k0 = 0; k0 < DIN; k0 += 32) {
        // A tile: 128 rows x 32 cols (float4 loads, tf32 rounding on store)
#pragma unroll
        for (int i = 0; i < 4; i++) {
            int f = tid + i * 256;
            int row = f >> 3, cv = f & 7;
            float4 v = *(const float4*)&x[(size_t)(m0 + row) * DIN + k0 + cv * 4];
            v.x = f2tf32(v.x); v.y = f2tf32(v.y); v.z = f2tf32(v.z); v.w = f2tf32(v.w);
            *(float4*)&As[row * 36 + cv * 4] = v;
        }
        // B tile: 32 rows(k) x 128 cols(n)
#pragma unroll
        for (int i = 0; i < 4; i++) {
            int f = tid + i * 256;
            int row = f >> 5, cv = f & 31;
            float4 v = *(const float4*)&Wx[(size_t)(k0 + row) * NGATE + n0 + cv * 4];
            v.x = f2tf32(v.x); v.y = f2tf32(v.y); v.z = f2tf32(v.z); v.w = f2tf32(v.w);
            *(float4*)&Bs[row * 136 + cv * 4] = v;
        }
        __syncthreads();

        const uint32_t* Au = (const uint32_t*)As;
        const uint32_t* Bu = (const uint32_t*)Bs;
#pragma unroll
        for (int k8 = 0; k8 < 4; k8++) {
            int kb = k8 * 8;
            uint32_t afr[2][4];
#pragma unroll
            for (int mt = 0; mt < 2; mt++) {
                int r = wm * 32 + mt * 16 + g;
                afr[mt][0] = Au[r * 36 + kb + t4];
                afr[mt][1] = Au[(r + 8) * 36 + kb + t4];
                afr[mt][2] = Au[r * 36 + kb + t4 + 4];
                afr[mt][3] = Au[(r + 8) * 36 + kb + t4 + 4];
            }
#pragma unroll
            for (int nt = 0; nt < 8; nt++) {
                uint32_t bfr[2];
                int cc = wn * 64 + nt * 8 + g;
                bfr[0] = Bu[(kb + t4) * 136 + cc];
                bfr[1] = Bu[(kb + t4 + 4) * 136 + cc];
#pragma unroll
                for (int mt = 0; mt < 2; mt++) mma_tf32(acc[mt][nt], afr[mt], bfr);
            }
        }
        __syncthreads();
    }

    // Epilogue: G = acc + bias
#pragma unroll
    for (int mt = 0; mt < 2; mt++) {
#pragma unroll
        for (int nt = 0; nt < 8; nt++) {
            int r = m0 + wm * 32 + mt * 16 + g;
            int c = n0 + wn * 64 + nt * 8 + 2 * t4;
            float b0 = bias[c], b1 = bias[c + 1];
            float2 v0 = make_float2(acc[mt][nt][0] + b0, acc[mt][nt][1] + b1);
            float2 v1 = make_float2(acc[mt][nt][2] + b0, acc[mt][nt][3] + b1);
            *(float2*)&g_G[(size_t)r * NGATE + c]       = v0;
            *(float2*)&g_G[(size_t)(r + 8) * NGATE + c] = v1;
        }
    }
}

// ---------------- recurrent step (fused GEMM + LSTM pointwise) ----------------
// One launch per timestep. Grid = 128 blocks; block handles gate-columns
// [j0, j0+8) of EACH of the 4 gates (cols j, H+j, 2H+j, 3H+j of Wh).
// 8 warps; warp w covers batch rows [16w, 16w+16). Mask applied to h on A-load.

__global__ __launch_bounds__(256) void lstm_step(const float* __restrict__ mask,
                                                 const float* __restrict__ Wh,
                                                 float* __restrict__ out_hs,
                                                 int t) {
    __shared__ float As[128 * 36];
    __shared__ float Bs[32 * 40];

    const float* h_in  = g_h[t & 1];
    float*       h_out = g_h[(t + 1) & 1];
    const float* mrow  = mask + (size_t)t * BATCH;

    const int tid  = threadIdx.x;
    const int warp = tid >> 5, lane = tid & 31;
    const int g  = lane >> 2, t4 = lane & 3;
    const int j0 = blockIdx.x * 8;
    const int rb = warp * 16;

    float acc[4][4];
#pragma unroll
    for (int a = 0; a < 4; a++)
#pragma unroll
        for (int c = 0; c < 4; c++) acc[a][c] = 0.f;

    for (int k0 = 0; k0 < HID; k0 += 32) {
        // A tile: masked h, 128 x 32
#pragma unroll
        for (int i = 0; i < 4; i++) {
            int f = tid + i * 256;
            int row = f >> 3, cv = f & 7;
            float sc = 1.0f - mrow[row];
            float4 v = *(const float4*)&h_in[row * HID + k0 + cv * 4];
            v.x = f2tf32(v.x * sc); v.y = f2tf32(v.y * sc);
            v.z = f2tf32(v.z * sc); v.w = f2tf32(v.w * sc);
            *(float4*)&As[row * 36 + cv * 4] = v;
        }
        // B tile: 4 gates x 32(k) x 8(cols)
        {
            int k = tid >> 3, jj = tid & 7;
#pragma unroll
            for (int gate = 0; gate < 4; gate++) {
                float w = Wh[(size_t)(k0 + k) * NGATE + gate * HID + j0 + jj];
                Bs[k * 40 + gate * 8 + jj] = f2tf32(w);
            }
        }
        __syncthreads();

        const uint32_t* Au = (const uint32_t*)As;
        const uint32_t* Bu = (const uint32_t*)Bs;
#pragma unroll
        for (int k8 = 0; k8 < 4; k8++) {
            int kb = k8 * 8;
            uint32_t afr[4];
            afr[0] = Au[(rb + g) * 36 + kb + t4];
            afr[1] = Au[(rb + g + 8) * 36 + kb + t4];
            afr[2] = Au[(rb + g) * 36 + kb + t4 + 4];
            afr[3] = Au[(rb + g + 8) * 36 + kb + t4 + 4];
#pragma unroll
            for (int gate = 0; gate < 4; gate++) {
                uint32_t bfr[2];
                bfr[0] = Bu[(kb + t4) * 40 + gate * 8 + g];
                bfr[1] = Bu[(kb + t4 + 4) * 40 + gate * 8 + g];
                mma_tf32(acc[gate], afr, bfr);
            }
        }
        __syncthreads();
    }

    // Epilogue: combine with precomputed x@Wx+b, do LSTM pointwise.
#pragma unroll
    for (int p = 0; p < 4; p++) {
        int pr = p >> 1, pc = p & 1;
        int row = rb + g + pr * 8;           // batch index
        int col = j0 + 2 * t4 + pc;          // hidden index
        size_t gb = ((size_t)t * BATCH + row) * NGATE;
        float iv = acc[0][p] + g_G[gb + col];
        float fv = acc[1][p] + g_G[gb + HID + col];
        float ov = acc[2][p] + g_G[gb + 2 * HID + col];
        float gv = acc[3][p] + g_G[gb + 3 * HID + col];
        float cprev = g_c[row * HID + col] * (1.0f - mrow[row]);
        float cn = sigmoidf_fast(fv) * cprev + sigmoidf_fast(iv) * tanhf_fast(gv);
        float hn = sigmoidf_fast(ov) * tanhf_fast(cn);
        g_c[row * HID + col]  = cn;
        h_out[row * HID + col] = hn;
        out_hs[((size_t)t * BATCH + row) * HID + col] = hn;
    }
}

// ---------------- final state writeback ----------------

__global__ void write_final(float* __restrict__ out) {
    int idx = blockIdx.x * blockDim.x + threadIdx.x;
    if (idx < BATCH * HID) {
        int b = idx / HID, j = idx % HID;
        size_t base = (size_t)T_STEPS * BATCH * HID;
        out[base + (size_t)b * 2 * HID + j]       = g_c[idx];
        out[base + (size_t)b * 2 * HID + HID + j] = g_h[T_STEPS & 1][idx];
    }
}

// ---------------- launch ----------------

extern "C" void kernel_launch(void* const* d_in, const int* in_sizes, int n_in,
                              void* d_out, int out_size) {
    const float* x    = (const float*)d_in[0];  // [T,B,D]
    const float* mask = (const float*)d_in[1];  // [T,B,1]
    const float* csh  = (const float*)d_in[2];  // [B,2H]
    const float* Wx   = (const float*)d_in[3];  // [D,4H]
    const float* Wh   = (const float*)d_in[4];  // [H,4H]
    const float* bias = (const float*)d_in[5];  // [4H]
    float* out = (float*)d_out;

    init_state<<<(BATCH * HID + 255) / 256, 256>>>(csh);

    dim3 pg_grid(NGATE / 128, (T_STEPS * BATCH) / 128);  // (32, 256)
    pregemm<<<pg_grid, 256>>>(x, Wx, bias);

    for (int t = 0; t < T_STEPS; t++)
        lstm_step<<<128, 256>>>(mask, Wh, out, t);

    write_final<<<(BATCH * HID + 255) / 256, 256>>>(out);
}

// round 3
// speedup vs baseline: 1.7572x; 1.7572x over previous
#include <cuda_runtime.h>
#include <cstdint>

#define T_STEPS 256
#define BATCH   128
#define DIN     1024
#define HID     1024
#define NGATE   4096  // 4*HID
#define NBLK    128

// Scratch (device globals; no allocation allowed in kernel_launch).
__device__ float g_G[(size_t)T_STEPS * BATCH * NGATE];  // precomputed x@Wx + b  (512 MB)
__device__ float g_h[2][BATCH * HID];                   // double-buffered hidden state
__device__ float g_c[BATCH * HID];                      // cell state
__device__ unsigned g_cnt;                              // barrier arrive counter
__device__ volatile unsigned g_gen;                     // barrier generation

// ---------------- helpers ----------------

__device__ __forceinline__ float f2tf32(float x) {
    uint32_t u;
    asm("cvt.rna.tf32.f32 %0, %1;" : "=r"(u) : "f"(x));
    return __uint_as_float(u);
}

__device__ __forceinline__ void mma_tf32(float c[4], const uint32_t a[4], const uint32_t b[2]) {
    asm volatile(
        "mma.sync.aligned.m16n8k8.row.col.f32.tf32.tf32.f32 "
        "{%0,%1,%2,%3}, {%4,%5,%6,%7}, {%8,%9}, {%0,%1,%2,%3};"
        : "+f"(c[0]), "+f"(c[1]), "+f"(c[2]), "+f"(c[3])
        : "r"(a[0]), "r"(a[1]), "r"(a[2]), "r"(a[3]), "r"(b[0]), "r"(b[1]));
}

__device__ __forceinline__ float sigmoidf_fast(float x) {
    x = fminf(fmaxf(x, -30.f), 30.f);
    return __fdividef(1.f, 1.f + __expf(-x));
}

__device__ __forceinline__ float tanhf_fast(float x) {
    x = fminf(fmaxf(x, -15.f), 15.f);
    float e = __expf(2.f * x);
    return __fdividef(e - 1.f, e + 1.f);
}

// Software grid barrier. All NBLK blocks are co-resident (1 block/SM, 128<148).
__device__ __forceinline__ void grid_sync(unsigned step) {
    __syncthreads();
    if (threadIdx.x == 0) {
        __threadfence();
        unsigned a = atomicAdd(&g_cnt, 1u);
        if (a == gridDim.x - 1) {
            g_cnt = 0;
            __threadfence();
            g_gen = step + 1;
        } else {
            while (g_gen < step + 1) __nanosleep(32);
        }
        __threadfence();
    }
    __syncthreads();
}

// ---------------- init state + barrier ----------------

__global__ void init_state(const float* __restrict__ csh) {
    int idx = blockIdx.x * blockDim.x + threadIdx.x;
    if (idx == 0) { g_cnt = 0; g_gen = 0; }
    if (idx < BATCH * HID) {
        int b = idx / HID, j = idx % HID;
        g_c[idx]    = csh[b * 2 * HID + j];          // cell first
        g_h[0][idx] = csh[b * 2 * HID + HID + j];    // hidden second
    }
}

// ---------------- pre-GEMM: G = x @ Wx + bias ----------------
// M = T*B = 32768, N = 4096, K = 1024. Tile 128x128x32, 256 threads.

__global__ __launch_bounds__(256) void pregemm(const float* __restrict__ x,
                                               const float* __restrict__ Wx,
                                               const float* __restrict__ bias) {
    __shared__ float As[128 * 36];
    __shared__ float Bs[32 * 136];

    const int tid  = threadIdx.x;
    const int warp = tid >> 5, lane = tid & 31;
    const int g  = lane >> 2, t4 = lane & 3;
    const int wm = warp >> 1, wn = warp & 1;
    const int m0 = blockIdx.y * 128;
    const int n0 = blockIdx.x * 128;

    float acc[2][8][4];
#pragma unroll
    for (int a = 0; a < 2; a++)
#pragma unroll
        for (int b = 0; b < 8; b++)
#pragma unroll
            for (int c = 0; c < 4; c++) acc[a][b][c] = 0.f;

    for (int k0 = 0; k0 < DIN; k0 += 32) {
#pragma unroll
        for (int i = 0; i < 4; i++) {
            int f = tid + i * 256;
            int row = f >> 3, cv = f & 7;
            float4 v = *(const float4*)&x[(size_t)(m0 + row) * DIN + k0 + cv * 4];
            v.x = f2tf32(v.x); v.y = f2tf32(v.y); v.z = f2tf32(v.z); v.w = f2tf32(v.w);
            *(float4*)&As[row * 36 + cv * 4] = v;
        }
#pragma unroll
        for (int i = 0; i < 4; i++) {
            int f = tid + i * 256;
            int row = f >> 5, cv = f & 31;
            float4 v = *(const float4*)&Wx[(size_t)(k0 + row) * NGATE + n0 + cv * 4];
            v.x = f2tf32(v.x); v.y = f2tf32(v.y); v.z = f2tf32(v.z); v.w = f2tf32(v.w);
            *(float4*)&Bs[row * 136 + cv * 4] = v;
        }
        __syncthreads();

        const uint32_t* Au = (const uint32_t*)As;
        const uint32_t* Bu = (const uint32_t*)Bs;
#pragma unroll
        for (int k8 = 0; k8 < 4; k8++) {
            int kb = k8 * 8;
            uint32_t afr[2][4];
#pragma unroll
            for (int mt = 0; mt < 2; mt++) {
                int r = wm * 32 + mt * 16 + g;
                afr[mt][0] = Au[r * 36 + kb + t4];
                afr[mt][1] = Au[(r + 8) * 36 + kb + t4];
                afr[mt][2] = Au[r * 36 + kb + t4 + 4];
                afr[mt][3] = Au[(r + 8) * 36 + kb + t4 + 4];
            }
#pragma unroll
            for (int nt = 0; nt < 8; nt++) {
                uint32_t bfr[2];
                int cc = wn * 64 + nt * 8 + g;
                bfr[0] = Bu[(kb + t4) * 136 + cc];
                bfr[1] = Bu[(kb + t4 + 4) * 136 + cc];
#pragma unroll
                for (int mt = 0; mt < 2; mt++) mma_tf32(acc[mt][nt], afr[mt], bfr);
            }
        }
        __syncthreads();
    }

#pragma unroll
    for (int mt = 0; mt < 2; mt++) {
#pragma unroll
        for (int nt = 0; nt < 8; nt++) {
            int r = m0 + wm * 32 + mt * 16 + g;
            int c = n0 + wn * 64 + nt * 8 + 2 * t4;
            float b0 = bias[c], b1 = bias[c + 1];
            float2 v0 = make_float2(acc[mt][nt][0] + b0, acc[mt][nt][1] + b1);
            float2 v1 = make_float2(acc[mt][nt][2] + b0, acc[mt][nt][3] + b1);
            *(float2*)&g_G[(size_t)r * NGATE + c]       = v0;
            *(float2*)&g_G[(size_t)(r + 8) * NGATE + c] = v1;
        }
    }
}

// ---------------- persistent recurrence ----------------
// 128 blocks, 256 threads (8 warps). Block b owns gate-columns [8b, 8b+8) of
// each of the 4 gates. Wh slice (1024 x 32) lives in SMEM in mma-fragment
// order for the whole kernel. Warp w owns batch rows [16w, 16w+16): A tiles
// stage per-warp (syncwarp only), double-buffered 64-wide k-chunks.
// One software grid barrier per timestep.

#define A_STRIDE 68              // 64 + 4 pad, conflict-free frag loads
#define A_BUF    (16 * A_STRIDE) // 1088 floats per buffer
#define BFRAG_FLOATS 32768       // 128 kblocks * 4 gates * 64
#define SMEM_FLOATS (BFRAG_FLOATS + 8 * 2 * A_BUF)

__global__ __launch_bounds__(256, 1) void lstm_persistent(
        const float* __restrict__ mask,
        const float* __restrict__ Wh,
        float* __restrict__ out_hs) {
    extern __shared__ float smem[];
    float* Bfrag = smem;                 // 128 KB
    float* Ast   = smem + BFRAG_FLOATS;  // 8 warps * 2 bufs * 1088 floats

    const int tid  = threadIdx.x;
    const int warp = tid >> 5, lane = tid & 31;
    const int g  = lane >> 2, t4 = lane & 3;
    const int j0 = blockIdx.x * 8;
    const int rb = warp * 16;
    const int hi = lane >> 4;            // staging row parity
    float* Aw = Ast + warp * 2 * A_BUF;

    // ---- preload Wh fragments (once per launch) ----
    // Bfrag[kblock*256 + gate*64 + (g8*4+t4v)*2 + s] = tf32(Wh[kblock*8+s*4+t4v][gate*H + j0 + g8])
    for (int idx = tid; idx < BFRAG_FLOATS; idx += 256) {
        int g8   = idx & 7;
        int gate = (idx >> 3) & 3;
        int k    = idx >> 5;
        float v = f2tf32(Wh[(size_t)k * NGATE + gate * HID + j0 + g8]);
        int kblock = k >> 3, t4v = k & 3, s = (k >> 2) & 1;
        Bfrag[kblock * 256 + gate * 64 + (g8 * 4 + t4v) * 2 + s] = v;
    }
    __syncthreads();

    for (int t = 0; t < T_STEPS; t++) {
        const float* __restrict__ h_in  = g_h[t & 1];
        float*       __restrict__ h_out = g_h[(t + 1) & 1];
        const float* mrow = mask + (size_t)t * BATCH;

        // per-step mask scales
        float msk[8];
#pragma unroll
        for (int i = 0; i < 8; i++) msk[i] = 1.0f - mrow[rb + 2 * i + hi];
        float emsk0 = 1.0f - mrow[rb + g];
        float emsk1 = 1.0f - mrow[rb + g + 8];

        // prefetch epilogue G values (DRAM; hidden under the mainloop)
        float preG[4][4];
#pragma unroll
        for (int p = 0; p < 4; p++) {
            int row = rb + g + (p >> 1) * 8;
            int col = j0 + 2 * t4 + (p & 1);
            size_t gb = ((size_t)t * BATCH + row) * NGATE + col;
#pragma unroll
            for (int gate = 0; gate < 4; gate++)
                preG[gate][p] = __ldg(&g_G[gb + gate * HID]);
        }

        float acc[4][4];
#pragma unroll
        for (int a = 0; a < 4; a++)
#pragma unroll
            for (int c = 0; c < 4; c++) acc[a][c] = 0.f;

        // stage chunk 0
        float4 ld[8];
#pragma unroll
        for (int i = 0; i < 8; i++) {
            int f = i * 32 + lane;
            int row = f >> 4, quad = f & 15;
            ld[i] = *(const float4*)&h_in[(rb + row) * HID + quad * 4];
        }
#pragma unroll
        for (int i = 0; i < 8; i++) {
            int f = i * 32 + lane;
            int row = f >> 4, quad = f & 15;
            float4 v = ld[i];
            float sc = msk[i];
            v.x = f2tf32(v.x * sc); v.y = f2tf32(v.y * sc);
            v.z = f2tf32(v.z * sc); v.w = f2tf32(v.w * sc);
            *(float4*)&Aw[row * A_STRIDE + quad * 4] = v;
        }
        __syncwarp();

        for (int c = 0; c < 16; c++) {
            const uint32_t* Au = (const uint32_t*)(Aw + (c & 1) * A_BUF);
            // prefetch next chunk into registers
            if (c < 15) {
#pragma unroll
                for (int i = 0; i < 8; i++) {
                    int f = i * 32 + lane;
                    int row = f >> 4, quad = f & 15;
                    ld[i] = *(const float4*)&h_in[(rb + row) * HID + (c + 1) * 64 + quad * 4];
                }
            }
#pragma unroll
            for (int kb8 = 0; kb8 < 8; kb8++) {
                int kk = kb8 * 8;
                uint32_t afr[4];
                afr[0] = Au[g * A_STRIDE + kk + t4];
                afr[1] = Au[(g + 8) * A_STRIDE + kk + t4];
                afr[2] = Au[g * A_STRIDE + kk + t4 + 4];
                afr[3] = Au[(g + 8) * A_STRIDE + kk + t4 + 4];
                const float* Bb = Bfrag + (c * 8 + kb8) * 256;
#pragma unroll
                for (int gate = 0; gate < 4; gate++) {
                    float2 bv = *(const float2*)&Bb[gate * 64 + lane * 2];
                    uint32_t bfr[2] = {__float_as_uint(bv.x), __float_as_uint(bv.y)};
                    mma_tf32(acc[gate], afr, bfr);
                }
            }
            // write next chunk to the other buffer
            if (c < 15) {
                float* An = Aw + ((c + 1) & 1) * A_BUF;
#pragma unroll
                for (int i = 0; i < 8; i++) {
                    int f = i * 32 + lane;
                    int row = f >> 4, quad = f & 15;
                    float4 v = ld[i];
                    float sc = msk[i];
                    v.x = f2tf32(v.x * sc); v.y = f2tf32(v.y * sc);
                    v.z = f2tf32(v.z * sc); v.w = f2tf32(v.w * sc);
                    *(float4*)&An[row * A_STRIDE + quad * 4] = v;
                }
            }
            __syncwarp();
        }

        // epilogue: LSTM pointwise + state/output writes
#pragma unroll
        for (int p = 0; p < 4; p++) {
            int row = rb + g + (p >> 1) * 8;
            int col = j0 + 2 * t4 + (p & 1);
            float iv = acc[0][p] + preG[0][p];
            float fv = acc[1][p] + preG[1][p];
            float ov = acc[2][p] + preG[2][p];
            float gv = acc[3][p] + preG[3][p];
            float em = (p >> 1) ? emsk1 : emsk0;
            float cprev = g_c[row * HID + col] * em;
            float cn = sigmoidf_fast(fv) * cprev + sigmoidf_fast(iv) * tanhf_fast(gv);
            float hn = sigmoidf_fast(ov) * tanhf_fast(cn);
            g_c[row * HID + col]   = cn;
            h_out[row * HID + col] = hn;
            out_hs[((size_t)t * BATCH + row) * HID + col] = hn;
        }

        grid_sync((unsigned)t);
    }
}

// ---------------- final state writeback ----------------

__global__ void write_final(float* __restrict__ out) {
    int idx = blockIdx.x * blockDim.x + threadIdx.x;
    if (idx < BATCH * HID) {
        int b = idx / HID, j = idx % HID;
        size_t base = (size_t)T_STEPS * BATCH * HID;
        out[base + (size_t)b * 2 * HID + j]       = g_c[idx];
        out[base + (size_t)b * 2 * HID + HID + j] = g_h[T_STEPS & 1][idx];
    }
}

// ---------------- launch ----------------

extern "C" void kernel_launch(void* const* d_in, const int* in_sizes, int n_in,
                              void* d_out, int out_size) {
    const float* x    = (const float*)d_in[0];  // [T,B,D]
    const float* mask = (const float*)d_in[1];  // [T,B,1]
    const float* csh  = (const float*)d_in[2];  // [B,2H]
    const float* Wx   = (const float*)d_in[3];  // [D,4H]
    const float* Wh   = (const float*)d_in[4];  // [H,4H]
    const float* bias = (const float*)d_in[5];  // [4H]
    float* out = (float*)d_out;

    // Not a stream op; capture-safe and idempotent (no static guards allowed).
    cudaFuncSetAttribute(lstm_persistent,
                         cudaFuncAttributeMaxDynamicSharedMemorySize,
                         SMEM_FLOATS * (int)sizeof(float));

    init_state<<<(BATCH * HID + 255) / 256, 256>>>(csh);

    dim3 pg_grid(NGATE / 128, (T_STEPS * BATCH) / 128);  // (32, 256)
    pregemm<<<pg_grid, 256>>>(x, Wx, bias);

    lstm_persistent<<<NBLK, 256, SMEM_FLOATS * sizeof(float)>>>(mask, Wh, out);

    write_final<<<(BATCH * HID + 255) / 256, 256>>>(out);
}

// round 5
// speedup vs baseline: 1.9096x; 1.0868x over previous
#include <cuda_runtime.h>
#include <cstdint>

#define T_STEPS 256
#define BATCH   128
#define DIN     1024
#define HID     1024
#define NGATE   4096  // 4*HID
#define NBLK    128

// Scratch (device globals; no allocation allowed in kernel_launch).
__device__ float g_G[(size_t)T_STEPS * BATCH * NGATE];  // precomputed x@Wx + b  (512 MB)
__device__ float g_h[2][BATCH * HID];                   // double-buffered hidden state
__device__ float g_c[BATCH * HID];                      // cell state
__device__ unsigned g_cnt;                              // barrier arrive counter
__device__ volatile unsigned g_gen;                     // barrier generation

// ---------------- helpers ----------------

__device__ __forceinline__ float f2tf32(float x) {
    uint32_t u;
    asm("cvt.rna.tf32.f32 %0, %1;" : "=r"(u) : "f"(x));
    return __uint_as_float(u);
}

__device__ __forceinline__ void mma_tf32(float c[4], const uint32_t a[4], const uint32_t b[2]) {
    asm volatile(
        "mma.sync.aligned.m16n8k8.row.col.f32.tf32.tf32.f32 "
        "{%0,%1,%2,%3}, {%4,%5,%6,%7}, {%8,%9}, {%0,%1,%2,%3};"
        : "+f"(c[0]), "+f"(c[1]), "+f"(c[2]), "+f"(c[3])
        : "r"(a[0]), "r"(a[1]), "r"(a[2]), "r"(a[3]), "r"(b[0]), "r"(b[1]));
}

__device__ __forceinline__ float sigmoidf_fast(float x) {
    x = fminf(fmaxf(x, -30.f), 30.f);
    return __fdividef(1.f, 1.f + __expf(-x));
}

__device__ __forceinline__ float tanhf_fast(float x) {
    x = fminf(fmaxf(x, -15.f), 15.f);
    float e = __expf(2.f * x);
    return __fdividef(e - 1.f, e + 1.f);
}

// Software grid barrier. All NBLK blocks are co-resident (1 block/SM, 128<148).
__device__ __forceinline__ void grid_sync(unsigned step) {
    __syncthreads();
    if (threadIdx.x == 0) {
        __threadfence();
        unsigned a = atomicAdd(&g_cnt, 1u);
        if (a == gridDim.x - 1) {
            g_cnt = 0;
            __threadfence();
            g_gen = step + 1;
        } else {
            while (g_gen < step + 1) __nanosleep(32);
        }
        __threadfence();
    }
    __syncthreads();
}

// ---------------- init state + barrier ----------------

__global__ void init_state(const float* __restrict__ csh) {
    int idx = blockIdx.x * blockDim.x + threadIdx.x;
    if (idx == 0) { g_cnt = 0; g_gen = 0; }
    if (idx < BATCH * HID) {
        int b = idx / HID, j = idx % HID;
        g_c[idx]    = csh[b * 2 * HID + j];          // cell first
        g_h[0][idx] = csh[b * 2 * HID + HID + j];    // hidden second
    }
}

// ---------------- pre-GEMM: G = x @ Wx + bias ----------------
// M = T*B = 32768, N = 4096, K = 1024. Tile 128x128x32, 256 threads,
// register-prefetch double-buffered pipeline, one __syncthreads per k-iter.

#define PG_TILE_A (128 * 36)
#define PG_TILE_B (32 * 136)
#define PG_STAGE  (PG_TILE_A + PG_TILE_B)   // 8960 floats
#define PG_SMEM_FLOATS (2 * PG_STAGE)       // 71680 bytes

__device__ __forceinline__ void pg_ldg(const float* __restrict__ x,
                                       const float* __restrict__ Wx,
                                       int m0, int n0, int k0, int tid,
                                       float4 lda[4], float4 ldb[4]) {
#pragma unroll
    for (int i = 0; i < 4; i++) {
        int f = tid + i * 256;
        int row = f >> 3, cv = f & 7;
        lda[i] = *(const float4*)&x[(size_t)(m0 + row) * DIN + k0 + cv * 4];
    }
#pragma unroll
    for (int i = 0; i < 4; i++) {
        int f = tid + i * 256;
        int row = f >> 5, cv = f & 31;
        ldb[i] = *(const float4*)&Wx[(size_t)(k0 + row) * NGATE + n0 + cv * 4];
    }
}

__device__ __forceinline__ void pg_sts(float* __restrict__ st, int tid,
                                       const float4 lda[4], const float4 ldb[4]) {
    float* As = st;
    float* Bs = st + PG_TILE_A;
#pragma unroll
    for (int i = 0; i < 4; i++) {
        int f = tid + i * 256;
        int row = f >> 3, cv = f & 7;
        float4 v = lda[i];
        v.x = f2tf32(v.x); v.y = f2tf32(v.y); v.z = f2tf32(v.z); v.w = f2tf32(v.w);
        *(float4*)&As[row * 36 + cv * 4] = v;
    }
#pragma unroll
    for (int i = 0; i < 4; i++) {
        int f = tid + i * 256;
        int row = f >> 5, cv = f & 31;
        float4 v = ldb[i];
        v.x = f2tf32(v.x); v.y = f2tf32(v.y); v.z = f2tf32(v.z); v.w = f2tf32(v.w);
        *(float4*)&Bs[row * 136 + cv * 4] = v;
    }
}

__global__ __launch_bounds__(256, 2) void pregemm(const float* __restrict__ x,
                                                  const float* __restrict__ Wx,
                                                  const float* __restrict__ bias) {
    extern __shared__ float sm[];

    const int tid  = threadIdx.x;
    const int warp = tid >> 5, lane = tid & 31;
    const int g  = lane >> 2, t4 = lane & 3;
    const int wm = warp >> 1, wn = warp & 1;
    const int m0 = blockIdx.y * 128;
    const int n0 = blockIdx.x * 128;

    float acc[2][8][4];
#pragma unroll
    for (int a = 0; a < 2; a++)
#pragma unroll
        for (int b = 0; b < 8; b++)
#pragma unroll
            for (int c = 0; c < 4; c++) acc[a][b][c] = 0.f;

    float4 lda[4], ldb[4];
    pg_ldg(x, Wx, m0, n0, 0, tid, lda, ldb);
    pg_sts(sm, tid, lda, ldb);
    __syncthreads();

    for (int kt = 0; kt < 32; kt++) {
        // prefetch next tile into registers (hidden under compute)
        if (kt < 31) pg_ldg(x, Wx, m0, n0, (kt + 1) * 32, tid, lda, ldb);

        const float* st = sm + (kt & 1) * PG_STAGE;
        const uint32_t* Au = (const uint32_t*)st;
        const uint32_t* Bu = (const uint32_t*)(st + PG_TILE_A);
#pragma unroll
        for (int k8 = 0; k8 < 4; k8++) {
            int kb = k8 * 8;
            uint32_t afr[2][4];
#pragma unroll
            for (int mt = 0; mt < 2; mt++) {
                int r = wm * 32 + mt * 16 + g;
                afr[mt][0] = Au[r * 36 + kb + t4];
                afr[mt][1] = Au[(r + 8) * 36 + kb + t4];
                afr[mt][2] = Au[r * 36 + kb + t4 + 4];
                afr[mt][3] = Au[(r + 8) * 36 + kb + t4 + 4];
            }
#pragma unroll
            for (int nt = 0; nt < 8; nt++) {
                uint32_t bfr[2];
                int cc = wn * 64 + nt * 8 + g;
                bfr[0] = Bu[(kb + t4) * 136 + cc];
                bfr[1] = Bu[(kb + t4 + 4) * 136 + cc];
#pragma unroll
                for (int mt = 0; mt < 2; mt++) mma_tf32(acc[mt][nt], afr[mt], bfr);
            }
        }

        if (kt < 31) pg_sts(sm + ((kt + 1) & 1) * PG_STAGE, tid, lda, ldb);
        __syncthreads();
    }

#pragma unroll
    for (int mt = 0; mt < 2; mt++) {
#pragma unroll
        for (int nt = 0; nt < 8; nt++) {
            int r = m0 + wm * 32 + mt * 16 + g;
            int c = n0 + wn * 64 + nt * 8 + 2 * t4;
            float b0 = bias[c], b1 = bias[c + 1];
            float2 v0 = make_float2(acc[mt][nt][0] + b0, acc[mt][nt][1] + b1);
            float2 v1 = make_float2(acc[mt][nt][2] + b0, acc[mt][nt][3] + b1);
            *(float2*)&g_G[(size_t)r * NGATE + c]       = v0;
            *(float2*)&g_G[(size_t)(r + 8) * NGATE + c] = v1;
        }
    }
}

// ---------------- persistent recurrence ----------------
// 128 blocks, 256 threads (8 warps). Block b owns gate-columns [8b, 8b+8) of
// each of the 4 gates. Wh slice lives in SMEM in packed fragment order
// (2x LDS.128 per kb8 covers all 4 gates). Warp w owns batch rows
// [16w, 16w+16): per-warp double-buffered A staging, syncwarp-only mainloop.
// G[t+1] and mask[t+1] prefetched during step t's mainloop.

#define A_STRIDE 68              // 64 + 4 pad, conflict-free frag loads
#define A_BUF    (16 * A_STRIDE) // 1088 floats per buffer
#define BFRAG_FLOATS 32768       // 128 kblocks * 256
#define SMEM_FLOATS (BFRAG_FLOATS + 8 * 2 * A_BUF)

__global__ __launch_bounds__(256, 1) void lstm_persistent(
        const float* __restrict__ mask,
        const float* __restrict__ Wh,
        float* __restrict__ out_hs) {
    extern __shared__ float smem[];
    float* Bfrag = smem;                 // 128 KB
    float* Ast   = smem + BFRAG_FLOATS;  // 8 warps * 2 bufs * 1088 floats

    const int tid  = threadIdx.x;
    const int warp = tid >> 5, lane = tid & 31;
    const int g  = lane >> 2, t4 = lane & 3;
    const int j0 = blockIdx.x * 8;
    const int rb = warp * 16;
    const int hi = lane >> 4;            // staging row parity
    const int colb = j0 + 2 * t4;        // even column base for float2 epilogue
    float* Aw = Ast + warp * 2 * A_BUF;

    // ---- preload Wh fragments (once per launch) ----
    // Layout per kblock (256 floats): [q][lane][gpair][s] with q = gate>>1,
    // gpair = gate&1, s = k-half. Mainloop: 2x LDS.128 per kb8, conflict-free.
    for (int idx = tid; idx < BFRAG_FLOATS; idx += 256) {
        int kb     = idx >> 8;
        int within = idx & 255;
        int q      = within >> 7;
        int rest   = within & 127;
        int lane_i = rest >> 2;
        int sub    = rest & 3;
        int gate   = q * 2 + (sub >> 1);
        int s      = sub & 1;
        int g8     = lane_i >> 2;
        int t4v    = lane_i & 3;
        int k      = kb * 8 + s * 4 + t4v;
        Bfrag[idx] = f2tf32(Wh[(size_t)k * NGATE + gate * HID + j0 + g8]);
    }
    __syncthreads();

    // per-step scalars for step 0
    float msk[8], emsk0, emsk1;
    float2 pG[4][2];
    {
        const float* mrow = mask;
#pragma unroll
        for (int i = 0; i < 8; i++) msk[i] = 1.0f - __ldg(&mrow[rb + 2 * i + hi]);
        emsk0 = 1.0f - __ldg(&mrow[rb + g]);
        emsk1 = 1.0f - __ldg(&mrow[rb + g + 8]);
#pragma unroll
        for (int r = 0; r < 2; r++) {
            size_t gb = ((size_t)(rb + g + r * 8)) * NGATE + colb;
#pragma unroll
            for (int gate = 0; gate < 4; gate++)
                pG[gate][r] = __ldg((const float2*)&g_G[gb + gate * HID]);
        }
    }

    for (int t = 0; t < T_STEPS; t++) {
        const float* __restrict__ h_in  = g_h[t & 1];
        float*       __restrict__ h_out = g_h[(t + 1) & 1];

        float nmsk[8] = {0.f, 0.f, 0.f, 0.f, 0.f, 0.f, 0.f, 0.f};
        float nem0 = 0.f, nem1 = 0.f;
        float2 nG[4][2];
#pragma unroll
        for (int gate = 0; gate < 4; gate++) {
            nG[gate][0] = make_float2(0.f, 0.f);
            nG[gate][1] = make_float2(0.f, 0.f);
        }

        float acc[4][4];
#pragma unroll
        for (int a = 0; a < 4; a++)
#pragma unroll
            for (int c = 0; c < 4; c++) acc[a][c] = 0.f;

        // stage chunk 0
        float4 ld[8];
#pragma unroll
        for (int i = 0; i < 8; i++) {
            int f = i * 32 + lane;
            int row = f >> 4, quad = f & 15;
            ld[i] = *(const float4*)&h_in[(rb + row) * HID + quad * 4];
        }
#pragma unroll
        for (int i = 0; i < 8; i++) {
            int f = i * 32 + lane;
            int row = f >> 4, quad = f & 15;
            float4 v = ld[i];
            float sc = msk[i];
            v.x = f2tf32(v.x * sc); v.y = f2tf32(v.y * sc);
            v.z = f2tf32(v.z * sc); v.w = f2tf32(v.w * sc);
            *(float4*)&Aw[row * A_STRIDE + quad * 4] = v;
        }
        __syncwarp();

        for (int c = 0; c < 16; c++) {
            const uint32_t* Au = (const uint32_t*)(Aw + (c & 1) * A_BUF);
            // prefetch next chunk into registers
            if (c < 15) {
#pragma unroll
                for (int i = 0; i < 8; i++) {
                    int f = i * 32 + lane;
                    int row = f >> 4, quad = f & 15;
                    ld[i] = *(const float4*)&h_in[(rb + row) * HID + (c + 1) * 64 + quad * 4];
                }
            }
            // mid-loop: prefetch next step's G and mask (independent of barrier)
            if (c == 7 && t + 1 < T_STEPS) {
                const float* nmrow = mask + (size_t)(t + 1) * BATCH;
#pragma unroll
                for (int i = 0; i < 8; i++) nmsk[i] = 1.0f - __ldg(&nmrow[rb + 2 * i + hi]);
                nem0 = 1.0f - __ldg(&nmrow[rb + g]);
                nem1 = 1.0f - __ldg(&nmrow[rb + g + 8]);
#pragma unroll
                for (int r = 0; r < 2; r++) {
                    size_t gb = ((size_t)(t + 1) * BATCH + rb + g + r * 8) * NGATE + colb;
#pragma unroll
                    for (int gate = 0; gate < 4; gate++)
                        nG[gate][r] = __ldg((const float2*)&g_G[gb + gate * HID]);
                }
            }
#pragma unroll
            for (int kb8 = 0; kb8 < 8; kb8++) {
                int kk = kb8 * 8;
                uint32_t afr[4];
                afr[0] = Au[g * A_STRIDE + kk + t4];
                afr[1] = Au[(g + 8) * A_STRIDE + kk + t4];
                afr[2] = Au[g * A_STRIDE + kk + t4 + 4];
                afr[3] = Au[(g + 8) * A_STRIDE + kk + t4 + 4];
                const float* Bb = Bfrag + (c * 8 + kb8) * 256;
                float4 bA = *(const float4*)&Bb[lane * 4];        // gates 0,1
                float4 bB = *(const float4*)&Bb[128 + lane * 4];  // gates 2,3
                uint32_t b0[2] = {__float_as_uint(bA.x), __float_as_uint(bA.y)};
                uint32_t b1[2] = {__float_as_uint(bA.z), __float_as_uint(bA.w)};
                uint32_t b2[2] = {__float_as_uint(bB.x), __float_as_uint(bB.y)};
                uint32_t b3[2] = {__float_as_uint(bB.z), __float_as_uint(bB.w)};
                mma_tf32(acc[0], afr, b0);
                mma_tf32(acc[1], afr, b1);
                mma_tf32(acc[2], afr, b2);
                mma_tf32(acc[3], afr, b3);
            }
            // write next chunk to the other buffer
            if (c < 15) {
                float* An = Aw + ((c + 1) & 1) * A_BUF;
#pragma unroll
                for (int i = 0; i < 8; i++) {
                    int f = i * 32 + lane;
                    int row = f >> 4, quad = f & 15;
                    float4 v = ld[i];
                    float sc = msk[i];
                    v.x = f2tf32(v.x * sc); v.y = f2tf32(v.y * sc);
                    v.z = f2tf32(v.z * sc); v.w = f2tf32(v.w * sc);
                    *(float4*)&An[row * A_STRIDE + quad * 4] = v;
                }
            }
            __syncwarp();
        }

        // epilogue: LSTM pointwise + state/output writes (float2 per row-half)
#pragma unroll
        for (int r = 0; r < 2; r++) {
            int row = rb + g + r * 8;
            float em = r ? emsk1 : emsk0;
            float2 cp = *(const float2*)&g_c[row * HID + colb];
            float iv0 = acc[0][2 * r]     + pG[0][r].x;
            float iv1 = acc[0][2 * r + 1] + pG[0][r].y;
            float fv0 = acc[1][2 * r]     + pG[1][r].x;
            float fv1 = acc[1][2 * r + 1] + pG[1][r].y;
            float ov0 = acc[2][2 * r]     + pG[2][r].x;
            float ov1 = acc[2][2 * r + 1] + pG[2][r].y;
            float gv0 = acc[3][2 * r]     + pG[3][r].x;
            float gv1 = acc[3][2 * r + 1] + pG[3][r].y;
            float cn0 = sigmoidf_fast(fv0) * (cp.x * em) + sigmoidf_fast(iv0) * tanhf_fast(gv0);
            float cn1 = sigmoidf_fast(fv1) * (cp.y * em) + sigmoidf_fast(iv1) * tanhf_fast(gv1);
            float hn0 = sigmoidf_fast(ov0) * tanhf_fast(cn0);
            float hn1 = sigmoidf_fast(ov1) * tanhf_fast(cn1);
            *(float2*)&g_c[row * HID + colb]   = make_float2(cn0, cn1);
            *(float2*)&h_out[row * HID + colb] = make_float2(hn0, hn1);
            *(float2*)&out_hs[((size_t)t * BATCH + row) * HID + colb] = make_float2(hn0, hn1);
        }

        grid_sync((unsigned)t);

        // rotate prefetched step scalars
#pragma unroll
        for (int i = 0; i < 8; i++) msk[i] = nmsk[i];
        emsk0 = nem0; emsk1 = nem1;
#pragma unroll
        for (int gate = 0; gate < 4; gate++) {
            pG[gate][0] = nG[gate][0];
            pG[gate][1] = nG[gate][1];
        }
    }
}

// ---------------- final state writeback ----------------

__global__ void write_final(float* __restrict__ out) {
    int idx = blockIdx.x * blockDim.x + threadIdx.x;
    if (idx < BATCH * HID) {
        int b = idx / HID, j = idx % HID;
        size_t base = (size_t)T_STEPS * BATCH * HID;
        out[base + (size_t)b * 2 * HID + j]       = g_c[idx];
        out[base + (size_t)b * 2 * HID + HID + j] = g_h[T_STEPS & 1][idx];
    }
}

// ---------------- launch ----------------

extern "C" void kernel_launch(void* const* d_in, const int* in_sizes, int n_in,
                              void* d_out, int out_size) {
    const float* x    = (const float*)d_in[0];  // [T,B,D]
    const float* mask = (const float*)d_in[1];  // [T,B,1]
    const float* csh  = (const float*)d_in[2];  // [B,2H]
    const float* Wx   = (const float*)d_in[3];  // [D,4H]
    const float* Wh   = (const float*)d_in[4];  // [H,4H]
    const float* bias = (const float*)d_in[5];  // [4H]
    float* out = (float*)d_out;

    // Not stream ops; capture-safe and idempotent.
    cudaFuncSetAttribute(lstm_persistent,
                         cudaFuncAttributeMaxDynamicSharedMemorySize,
                         SMEM_FLOATS * (int)sizeof(float));
    cudaFuncSetAttribute(pregemm,
                         cudaFuncAttributeMaxDynamicSharedMemorySize,
                         PG_SMEM_FLOATS * (int)sizeof(float));

    init_state<<<(BATCH * HID + 255) / 256, 256>>>(csh);

    dim3 pg_grid(NGATE / 128, (T_STEPS * BATCH) / 128);  // (32, 256)
    pregemm<<<pg_grid, 256, PG_SMEM_FLOATS * sizeof(float)>>>(x, Wx, bias);

    lstm_persistent<<<NBLK, 256, SMEM_FLOATS * sizeof(float)>>>(mask, Wh, out);

    write_final<<<(BATCH * HID + 255) / 256, 256>>>(out);
}